// round 7
// baseline (speedup 1.0000x reference)
#include <cuda_runtime.h>

// NLSearch: vid0, vid1 (1,3,32,256,256) f32. Query grid 64x64 stride 4,
// patch 7x7, shift window 8x8 (offsets -4..3), K=7.
// Block = 128 threads (4 warps); warp w computes shift rows 2w and 2w+1,
// streaming v1 rows once each with register-carried v0 rows.
// Staging via aligned LDG.128 (border CTAs take a scalar reflect path).
// Output float32: [0,86016) dists (1,1,12288,7); [86016,344064) inds (..,7,3).

#define V1_CSTR 197   // 14*14=196 padded to 197 (odd -> conflict-free)
#define V0_CSTR 49    // 7*7 (odd -> conflict-free)

__device__ __forceinline__ int refl(int x) {
    x = x < 0 ? -x : x;
    return x > 255 ? 510 - x : x;
}

__global__ void __launch_bounds__(128, 7)
nls_kernel(const float* __restrict__ vid0,
           const float* __restrict__ vid1,
           float* __restrict__ out)
{
    __shared__ float v1s[32 * V1_CSTR]; // [c][rr*14+cc], rows qh-7..qh+6, cols qw-7..qw+6
    __shared__ float v0s[32 * V0_CSTR]; // [c][ii*7+jj],  rows qh-3..qh+3, cols qw-3..qw+3
    __shared__ float sdist[64];

    const int b = blockIdx.x;
    const int t = b >> 12;
    const int r = b & 4095;
    const int n = r >> 6;
    const int v = r & 63;
    const int qh = n << 2;
    const int qw = v << 2;

    const int tid  = threadIdx.x;
    const int lane = tid & 31;
    const int w    = tid >> 5;        // warp 0..3 -> shift rows 2w, 2w+1

    const size_t toff = (size_t)t * 32 * 65536;

    // ---- stage (reflect applied) ----
    if (qw >= 8 && qw <= 248) {
        // vector path: columns in range, only rows need reflection.
        // v1: 14 rows x 4 quads (cols qw-8 .. qw+7), tid -> (quad, row, chan-half)
        {
            int pos = tid & 63;
            int q   = pos & 3;
            int rr  = pos >> 2;            // 0..15, valid < 14
            int ch0 = (tid >> 6) << 4;     // 0 or 16
            if (rr < 14) {
                int hg = refl(qh - 7 + rr);
                const float4* src =
                    (const float4*)(vid1 + toff + (hg << 8) + (qw - 8)) + q;
                float* dbase = v1s + rr * 14 + 4 * q - 1; // cc = 4q-1+e
#pragma unroll
                for (int k = 0; k < 16; k++) {
                    int c = ch0 + k;
                    float4 vv = src[(size_t)c << 14];   // c * 65536 floats
                    float* d = dbase + c * V1_CSTR;
                    if (q > 0) d[0] = vv.x;             // cc 4q-1 (>=3)
                    d[1] = vv.y;                        // cc 4q
                    d[2] = vv.z;                        // cc 4q+1
                    if (q < 3) d[3] = vv.w;             // cc 4q+2 (<=10)
                }
            }
        }
        // v0: 7 rows x 2 quads (cols qw-4 .. qw+3), tid -> (quad, row, chan-grp)
        {
            int pos = tid & 15;
            int q   = pos & 1;
            int ii  = pos >> 1;            // 0..7, valid < 7
            int cg  = (tid >> 4) << 2;     // 0,4,..,28
            if (ii < 7) {
                int hg = refl(qh - 3 + ii);
                const float4* src =
                    (const float4*)(vid0 + toff + (hg << 8) + (qw - 4)) + q;
                float* dbase = v0s + ii * 7 + 4 * q - 1; // cc = 4q-1+e
#pragma unroll
                for (int k = 0; k < 4; k++) {
                    int c = cg + k;
                    float4 vv = src[(size_t)c << 14];
                    float* d = dbase + c * V0_CSTR;
                    if (q > 0) d[0] = vv.x;             // cc 3
                    d[1] = vv.y;                        // cc 4q
                    d[2] = vv.z;                        // cc 4q+1
                    d[3] = vv.w;                        // cc 4q+2 (<=6)
                }
            }
        }
    } else {
        // scalar border path (qw in {0,4,252}): per-element column reflect
        for (int pos = tid; pos < 245; pos += 128) {
            if (pos < 196) {
                int rr = pos / 14;
                int cc = pos - rr * 14;
                int hg = refl(qh - 7 + rr);
                int wg = refl(qw - 7 + cc);
                const float* src = vid1 + toff + (hg << 8) + wg;
                float* dst = v1s + pos;
#pragma unroll 8
                for (int c = 0; c < 32; c++)
                    dst[c * V1_CSTR] = src[c << 16];
            } else {
                int idx = pos - 196;
                int ii = idx / 7;
                int jj = idx - ii * 7;
                int hg = refl(qh - 3 + ii);
                int wg = refl(qw - 3 + jj);
                const float* src = vid0 + toff + (hg << 8) + wg;
                float* dst = v0s + idx;
#pragma unroll 8
                for (int c = 0; c < 32; c++)
                    dst[c * V0_CSTR] = src[c << 16];
            }
        }
    }
    __syncthreads();

    // ---- compute: lane = channel; warp w owns shift rows 2w (A[0..7]) and
    // 2w+1 (A[8..15]). Stream b rows r = 2w..2w+7 once; a rows carried in regs.
    const float* a_base = v0s + lane * V0_CSTR;
    const float* b_base = v1s + lane * V1_CSTR + (2 * w) * 14;

    float A[16];
#pragma unroll
    for (int s = 0; s < 16; s++) A[s] = 0.f;

    float aPrev[7];
#pragma unroll
    for (int rr = 0; rr < 8; rr++) {
        float bb[14];
        const float* br = b_base + rr * 14;
#pragma unroll
        for (int j = 0; j < 14; j++) bb[j] = br[j];

        float aCur[7];
        if (rr <= 6) {
            const float* ar = a_base + rr * 7;
#pragma unroll
            for (int j = 0; j < 7; j++) aCur[j] = ar[j];
#pragma unroll
            for (int s = 0; s < 8; s++)
#pragma unroll
                for (int j = 0; j < 7; j++)
                    A[s] = fmaf(aCur[j], bb[j + s], A[s]);
        }
        if (rr >= 1) {
#pragma unroll
            for (int s = 0; s < 8; s++)
#pragma unroll
                for (int j = 0; j < 7; j++)
                    A[8 + s] = fmaf(aPrev[j], bb[j + s], A[8 + s]);
        }
        if (rr <= 6) {
#pragma unroll
            for (int j = 0; j < 7; j++) aPrev[j] = aCur[j];
        }
    }

    // ---- folded multi-value warp reduction: 16 values summed over 32 lanes.
    // After folding, even lane L holds total of value s = (L>>1)&15.
    {
        int nv = 16;
#pragma unroll
        for (int o = 16; o > 1; o >>= 1) {
            int half = nv >> 1;
            bool up = (lane & o) != 0;
#pragma unroll
            for (int k = 0; k < 8; k++) {
                if (k < half) {
                    float tmp  = up ? A[k] : A[k + half];
                    float recv = __shfl_xor_sync(0xffffffffu, tmp, o);
                    float keep = up ? A[k + half] : A[k];
                    A[k] = keep + recv;
                }
            }
            nv = half;
        }
        A[0] += __shfl_xor_sync(0xffffffffu, A[0], 1);
        if ((lane & 1) == 0)
            sdist[16 * w + ((lane >> 1) & 15)] = A[0];
    }
    __syncthreads();

    // ---- top-7 (warp 0): value desc, index asc tie-break ----
    if (w == 0) {
        float a0 = sdist[lane];
        float a1 = sdist[lane + 32];
        if (lane == 4) a1 += 1e30f;   // self shift idx 36 boosted for selection

        const int q = t * 4096 + n * 64 + v;
        float* dbase = out + (size_t)q * 7;
        float* ibase = out + 86016 + (size_t)q * 21;

#pragma unroll
        for (int k = 0; k < 7; k++) {
            float bv = (a0 >= a1) ? a0 : a1;
            int   bi = (a0 >= a1) ? lane : lane + 32;
#pragma unroll
            for (int o = 16; o > 0; o >>= 1) {
                float ov = __shfl_xor_sync(0xffffffffu, bv, o);
                int   oi = __shfl_xor_sync(0xffffffffu, bi, o);
                if (ov > bv || (ov == bv && oi < bi)) { bv = ov; bi = oi; }
            }
            if (bi == lane)      a0 = -3.4e38f;
            if (bi == lane + 32) a1 = -3.4e38f;
            if (lane == 0) {
                dbase[k] = sdist[bi];
                int s0 = bi >> 3;
                int s1 = bi & 7;
                ibase[k * 3 + 0] = (float)t;
                ibase[k * 3 + 1] = (float)refl(qh + s0 - 4);
                ibase[k * 3 + 2] = (float)refl(qw + s1 - 4);
            }
        }
    }
}

extern "C" void kernel_launch(void* const* d_in, const int* in_sizes, int n_in,
                              void* d_out, int out_size)
{
    const float* vid0 = (const float*)d_in[0];
    const float* vid1 = (const float*)d_in[1];
    float* out = (float*)d_out;
    nls_kernel<<<12288, 128>>>(vid0, vid1, out);
}

// round 8
// speedup vs baseline: 1.0985x; 1.0985x over previous
#include <cuda_runtime.h>

// NLSearch: vid0, vid1 (1,3,32,256,256) f32. Query grid 64x64 stride 4,
// patch 7x7, shift window 8x8 (offsets -4..3), K=7.
// R2 skeleton (proven fastest): 256 thr, warp = shift row, lane = channel,
// scalar LDS + sliding-window FFMA. This round: force 6 CTAs/SM (regs <= 42).
// Output float32: [0,86016) dists (1,1,12288,7); [86016,344064) inds (..,7,3).

#define V1_CSTR 197   // 14*14=196 padded to 197 (odd -> conflict-free)
#define V0_CSTR 49    // 7*7 = 49 (odd -> conflict-free)

__device__ __forceinline__ int refl(int x) {
    x = x < 0 ? -x : x;
    return x > 255 ? 510 - x : x;
}

__global__ void __launch_bounds__(256, 6)
nls_kernel(const float* __restrict__ vid0,
           const float* __restrict__ vid1,
           float* __restrict__ out)
{
    __shared__ float v1s[32 * V1_CSTR]; // [c][rr*14+cc], rows qh-7..qh+6
    __shared__ float v0s[32 * V0_CSTR]; // [c][ii*7+jj],  rows qh-3..qh+3
    __shared__ float sdist[64];

    const int b = blockIdx.x;
    const int t = b >> 12;
    const int r = b & 4095;
    const int n = r >> 6;
    const int v = r & 63;
    const int qh = n << 2;
    const int qw = v << 2;

    const int tid  = threadIdx.x;
    const int lane = tid & 31;
    const int w    = tid >> 5;       // warp id = s0 index (s0 = w - 4)

    // ---- stage: thread->(element) fixed once, loop channels ----
    if (tid < 196) {
        int rr = tid / 14;
        int cc = tid - rr * 14;
        int hg = refl(qh - 7 + rr);
        int wg = refl(qw - 7 + cc);
        const float* src = vid1 + (size_t)t * 32 * 65536 + (hg << 8) + wg;
        float* dst = v1s + tid;
#pragma unroll 8
        for (int c = 0; c < 32; c++) {
            dst[c * V1_CSTR] = src[c << 16];
        }
    } else if (tid < 196 + 49) {
        int idx = tid - 196;
        int ii = idx / 7;
        int jj = idx - ii * 7;
        int hg = refl(qh - 3 + ii);
        int wg = refl(qw - 3 + jj);
        const float* src = vid0 + (size_t)t * 32 * 65536 + (hg << 8) + wg;
        float* dst = v0s + idx;
#pragma unroll 8
        for (int c = 0; c < 32; c++) {
            dst[c * V0_CSTR] = src[c << 16];
        }
    }
    __syncthreads();

    // ---- compute: warp w = shift row s0; lane = channel c; loop i = patch row.
    // acc[s1] += v0[c][i][j] * v1[c][w+i][j+s1], j=0..6, s1=0..7.
    const float* a_base = v0s + lane * V0_CSTR;
    const float* b_base = v1s + lane * V1_CSTR + w * 14;

    float acc[8];
#pragma unroll
    for (int s = 0; s < 8; s++) acc[s] = 0.f;

#pragma unroll
    for (int i = 0; i < 7; i++) {
        float a[7], bb[14];
        const float* ar = a_base + i * 7;
        const float* br = b_base + i * 14;
#pragma unroll
        for (int j = 0; j < 7; j++)  a[j]  = ar[j];
#pragma unroll
        for (int j = 0; j < 14; j++) bb[j] = br[j];
#pragma unroll
        for (int s = 0; s < 8; s++)
#pragma unroll
            for (int j = 0; j < 7; j++)
                acc[s] = fmaf(a[j], bb[j + s], acc[s]);
    }

    // warp-reduce 8 partials (sum over channels)
#pragma unroll
    for (int s = 0; s < 8; s++) {
        float val = acc[s];
#pragma unroll
        for (int o = 16; o > 0; o >>= 1)
            val += __shfl_xor_sync(0xffffffffu, val, o);
        if (lane == 0) sdist[(w << 3) + s] = val;
    }
    __syncthreads();

    // ---- top-7 (warp 0): value desc, index asc tie-break ----
    if (w == 0) {
        float a0 = sdist[lane];
        float a1 = sdist[lane + 32];
        if (lane == 4) a1 += 1e30f;   // self shift idx 36 boosted for selection

        const int q = t * 4096 + n * 64 + v;
        float* dbase = out + (size_t)q * 7;
        float* ibase = out + 86016 + (size_t)q * 21;

#pragma unroll
        for (int k = 0; k < 7; k++) {
            float bv = (a0 >= a1) ? a0 : a1;
            int   bi = (a0 >= a1) ? lane : lane + 32;
#pragma unroll
            for (int o = 16; o > 0; o >>= 1) {
                float ov = __shfl_xor_sync(0xffffffffu, bv, o);
                int   oi = __shfl_xor_sync(0xffffffffu, bi, o);
                if (ov > bv || (ov == bv && oi < bi)) { bv = ov; bi = oi; }
            }
            if (bi == lane)      a0 = -3.4e38f;
            if (bi == lane + 32) a1 = -3.4e38f;
            if (lane == 0) {
                dbase[k] = sdist[bi];
                int s0 = bi >> 3;
                int s1 = bi & 7;
                ibase[k * 3 + 0] = (float)t;
                ibase[k * 3 + 1] = (float)refl(qh + s0 - 4);
                ibase[k * 3 + 2] = (float)refl(qw + s1 - 4);
            }
        }
    }
}

extern "C" void kernel_launch(void* const* d_in, const int* in_sizes, int n_in,
                              void* d_out, int out_size)
{
    const float* vid0 = (const float*)d_in[0];
    const float* vid1 = (const float*)d_in[1];
    float* out = (float*)d_out;
    nls_kernel<<<12288, 256>>>(vid0, vid1, out);
}